// round 5
// baseline (speedup 1.0000x reference)
#include <cuda_runtime.h>
#include <math.h>

// ---------------------------------------------------------------------------
// GCN_trad round 4:
//   - FUSED per-layer kernel: CSR aggregation -> smem Z tile -> register-tiled
//     FFMA GEMM (+bias+relu), fused pooling epilogue on final layer.
//   - PING-PONG buffers (fixes R3 race: aggregation gathers arbitrary rows,
//     so a layer must never write the buffer it reads).
// ---------------------------------------------------------------------------

#define NLMAX 100000
#define NSMAX 50000
#define ELMAX 1600000
#define ESMAX 800000
#define NG    512

__device__ __align__(256) float g_a_l[(size_t)NLMAX * 128];
__device__ __align__(256) float g_b_l[(size_t)NLMAX * 128];
__device__ __align__(256) float g_a_s[(size_t)NSMAX * 128];
__device__ __align__(256) float g_b_s[(size_t)NSMAX * 128];
__device__ __align__(256) float g_dinv_l[NLMAX];
__device__ __align__(256) float g_dinv_s[NSMAX];
__device__ __align__(256) float g_pool[NG * 128];
__device__ __align__(256) float g_gcnt[NG];
__device__ __align__(256) float g_m1[NG * 128];

__device__ __align__(256) int   g_rp_l[NLMAX + 1];
__device__ __align__(256) int   g_rp_s[NSMAX + 1];
__device__ __align__(256) int   g_cnts_l[NLMAX];
__device__ __align__(256) int   g_cnts_s[NSMAX];
__device__ __align__(256) int   g_bsums[1024];
__device__ __align__(256) int   g_ssrc_l[ELMAX];
__device__ __align__(256) float g_coef_l[ELMAX];
__device__ __align__(256) int   g_ssrc_s[ESMAX];
__device__ __align__(256) float g_coef_s[ESMAX];

// ---------------------------------------------------------------------------

__global__ void zero_f(float* __restrict__ p, int n) {
    int i = blockIdx.x * blockDim.x + threadIdx.x;
    if (i < n) p[i] = 0.f;
}
__global__ void zero_i(int* __restrict__ p, int n) {
    int i = blockIdx.x * blockDim.x + threadIdx.x;
    if (i < n) p[i] = 0;
}
__global__ void copy_i(const int* __restrict__ a, int* __restrict__ b, int n) {
    int i = blockIdx.x * blockDim.x + threadIdx.x;
    if (i < n) b[i] = a[i];
}

// deg (weighted) and edge-count histogram in one edge pass
__global__ void deg_hist(const int* __restrict__ dst, const float* __restrict__ w,
                         float* __restrict__ deg, int* __restrict__ cnt, int E) {
    int e = blockIdx.x * blockDim.x + threadIdx.x;
    if (e < E) {
        int d = dst[e];
        atomicAdd(&deg[d], w[e]);
        atomicAdd(&cnt[d], 1);
    }
}
__global__ void finish_dinv(float* __restrict__ d, int n) {
    int i = blockIdx.x * blockDim.x + threadIdx.x;
    if (i < n) d[i] = rsqrtf(1.0f + d[i]);
}

// --- scan (CSR rowptr) -----------------------------------------------------

__global__ void scan_tiles(const int* __restrict__ in, int* __restrict__ out,
                           int* __restrict__ bsums, int n) {
    __shared__ int sh[1024];
    int tid = threadIdx.x;
    int i = blockIdx.x * 1024 + tid;
    int v = (i < n) ? in[i] : 0;
    sh[tid] = v;
    __syncthreads();
#pragma unroll
    for (int off = 1; off < 1024; off <<= 1) {
        int t = (tid >= off) ? sh[tid - off] : 0;
        __syncthreads();
        sh[tid] += t;
        __syncthreads();
    }
    if (i < n) out[i + 1] = sh[tid];
    if (tid == 1023) bsums[blockIdx.x] = sh[1023];
}
__global__ void scan_sums(int* __restrict__ bsums, int nb) {
    __shared__ int sh[1024];
    int tid = threadIdx.x;
    sh[tid] = (tid < nb) ? bsums[tid] : 0;
    __syncthreads();
#pragma unroll
    for (int off = 1; off < 1024; off <<= 1) {
        int t = (tid >= off) ? sh[tid - off] : 0;
        __syncthreads();
        sh[tid] += t;
        __syncthreads();
    }
    if (tid < nb) bsums[tid] = sh[tid];
}
__global__ void scan_add(int* __restrict__ out, const int* __restrict__ bsums, int n) {
    int i = blockIdx.x * blockDim.x + threadIdx.x;
    if (i == 0) out[0] = 0;
    if (i < n) {
        int b = i >> 10;
        if (b > 0) out[i + 1] += bsums[b - 1];
    }
}

__global__ void scatter_edges(const int* __restrict__ src, const int* __restrict__ dst,
                              const float* __restrict__ w, const float* __restrict__ dinv,
                              int* __restrict__ off, int* __restrict__ ssrc,
                              float* __restrict__ coef, int E) {
    int e = blockIdx.x * blockDim.x + threadIdx.x;
    if (e >= E) return;
    int s = src[e], d = dst[e];
    int p = atomicAdd(&off[d], 1);
    ssrc[p] = s;
    coef[p] = w[e] * __ldg(&dinv[s]) * __ldg(&dinv[d]);
}

// --- vector helpers --------------------------------------------------------

template <int VW> struct Vec;
template <> struct Vec<4> { using T = float4; };
template <> struct Vec<2> { using T = float2; };
template <> struct Vec<1> { using T = float;  };

__device__ __forceinline__ float4 vscale(float4 v, float c) {
    return make_float4(v.x * c, v.y * c, v.z * c, v.w * c);
}
__device__ __forceinline__ float2 vscale(float2 v, float c) {
    return make_float2(v.x * c, v.y * c);
}
__device__ __forceinline__ float vscale(float v, float c) { return v * c; }
__device__ __forceinline__ float4 vfma(float4 a, float c, float4 v) {
    return make_float4(fmaf(c, v.x, a.x), fmaf(c, v.y, a.y),
                       fmaf(c, v.z, a.z), fmaf(c, v.w, a.w));
}
__device__ __forceinline__ float2 vfma(float2 a, float c, float2 v) {
    return make_float2(fmaf(c, v.x, a.x), fmaf(c, v.y, a.y));
}
__device__ __forceinline__ float vfma(float a, float c, float v) { return fmaf(c, v, a); }
__device__ __forceinline__ float4 vzero(float4*) { return make_float4(0.f,0.f,0.f,0.f); }
__device__ __forceinline__ float2 vzero(float2*) { return make_float2(0.f,0.f); }
__device__ __forceinline__ float  vzero(float*)  { return 0.f; }

// ---------------------------------------------------------------------------
// Fused layer: block = 128 rows. Phase 1: CSR-aggregate 128 rows into smem Z
// tile (warp per row, registers). Phase 2: Z[128,K] @ W[K,128] + bias, relu.
// Epilogue: write Hout (must differ from Hin!), or (POOL) run-compacted
// red.global.add into pool.
// ---------------------------------------------------------------------------
template <int K, bool POOL>
__global__ __launch_bounds__(256) void fused_layer(
    const float* __restrict__ Hin, const int* __restrict__ rowptr,
    const int* __restrict__ ssrc, const float* __restrict__ coef,
    const float* __restrict__ dinv, const float* __restrict__ W,
    const float* __restrict__ bias, float* __restrict__ Hout,
    const int* __restrict__ batch, float* __restrict__ pool, int N) {

    constexpr int BM = 128, BK = 16, PITCH = K + 4;
    constexpr int VW = K / 32;
    using VT = typename Vec<VW>::T;

    extern __shared__ float smem[];
    float* Zs = smem;                    // [BM][PITCH]
    float* Ws = smem + BM * PITCH;       // [BK][128]

    int tid = threadIdx.x;
    int lane = tid & 31;
    int warp = tid >> 5;                 // 0..7
    int row0 = blockIdx.x * BM;

    // ---- Phase 1: aggregate ----
    const VT* HinV = (const VT*)Hin;
#pragma unroll 1
    for (int r = warp; r < BM; r += 8) {
        int grow = row0 + r;
        VT acc = vzero((VT*)0);
        if (grow < N) {
            float di = __ldg(&dinv[grow]);
            acc = vscale(HinV[(size_t)grow * 32 + lane], di * di);
            int e  = __ldg(&rowptr[grow]);
            int e1 = __ldg(&rowptr[grow + 1]);
            for (; e + 1 < e1; e += 2) {
                int s0 = __ldg(&ssrc[e]);
                int s1 = __ldg(&ssrc[e + 1]);
                float c0 = __ldg(&coef[e]);
                float c1 = __ldg(&coef[e + 1]);
                VT v0 = HinV[(size_t)s0 * 32 + lane];
                VT v1 = HinV[(size_t)s1 * 32 + lane];
                acc = vfma(acc, c0, v0);
                acc = vfma(acc, c1, v1);
            }
            if (e < e1) {
                int s0 = __ldg(&ssrc[e]);
                float c0 = __ldg(&coef[e]);
                acc = vfma(acc, c0, HinV[(size_t)s0 * 32 + lane]);
            }
        }
        *(VT*)&Zs[r * PITCH + lane * VW] = acc;
    }
    __syncthreads();

    // ---- Phase 2: GEMM ----
    int tx = tid & 15;    // 16 col groups of 8
    int ty = tid >> 4;    // 16 row groups of 8
    int wr = tid >> 4;    // Ws row 0..15
    int wcol = (tid & 15) * 8;

    float accum[8][8];
#pragma unroll
    for (int i = 0; i < 8; i++)
#pragma unroll
        for (int j = 0; j < 8; j++) accum[i][j] = 0.f;

#pragma unroll
    for (int k0 = 0; k0 < K; k0 += BK) {
        *(float4*)&Ws[wr * 128 + wcol]     = *(const float4*)(W + (size_t)(k0 + wr) * 128 + wcol);
        *(float4*)&Ws[wr * 128 + wcol + 4] = *(const float4*)(W + (size_t)(k0 + wr) * 128 + wcol + 4);
        __syncthreads();
#pragma unroll
        for (int k = 0; k < BK; k++) {
            float a[8], b[8];
#pragma unroll
            for (int i = 0; i < 8; i++) a[i] = Zs[(ty * 8 + i) * PITCH + k0 + k];
            *(float4*)&b[0] = *(const float4*)&Ws[k * 128 + tx * 8];
            *(float4*)&b[4] = *(const float4*)&Ws[k * 128 + tx * 8 + 4];
#pragma unroll
            for (int i = 0; i < 8; i++)
#pragma unroll
                for (int j = 0; j < 8; j++) accum[i][j] = fmaf(a[i], b[j], accum[i][j]);
        }
        __syncthreads();
    }

    float bv[8];
    *(float4*)&bv[0] = *(const float4*)&bias[tx * 8];
    *(float4*)&bv[4] = *(const float4*)&bias[tx * 8 + 4];

    if (!POOL) {
#pragma unroll
        for (int i = 0; i < 8; i++) {
            int r = row0 + ty * 8 + i;
            if (r < N) {
                float4 o0, o1;
                o0.x = fmaxf(accum[i][0] + bv[0], 0.f);
                o0.y = fmaxf(accum[i][1] + bv[1], 0.f);
                o0.z = fmaxf(accum[i][2] + bv[2], 0.f);
                o0.w = fmaxf(accum[i][3] + bv[3], 0.f);
                o1.x = fmaxf(accum[i][4] + bv[4], 0.f);
                o1.y = fmaxf(accum[i][5] + bv[5], 0.f);
                o1.z = fmaxf(accum[i][6] + bv[6], 0.f);
                o1.w = fmaxf(accum[i][7] + bv[7], 0.f);
                *(float4*)(Hout + (size_t)r * 128 + tx * 8) = o0;
                *(float4*)(Hout + (size_t)r * 128 + tx * 8 + 4) = o1;
            }
        }
    } else {
        // Pooling epilogue: rows ty*8+i are consecutive; batch is sorted ->
        // accumulate runs with equal batch id, flush per run.
        float p0[4], p1[4];
        int curb = -1;
#pragma unroll
        for (int i = 0; i < 8; i++) {
            int r = row0 + ty * 8 + i;
            if (r >= N) break;
            int b = __ldg(&batch[r]);
            if (b != curb) {
                if (curb >= 0) {
                    float* dst0 = pool + (size_t)curb * 128 + tx * 8;
                    asm volatile("red.global.add.v4.f32 [%0], {%1,%2,%3,%4};"
                                 :: "l"(dst0), "f"(p0[0]), "f"(p0[1]), "f"(p0[2]), "f"(p0[3]) : "memory");
                    asm volatile("red.global.add.v4.f32 [%0], {%1,%2,%3,%4};"
                                 :: "l"(dst0 + 4), "f"(p1[0]), "f"(p1[1]), "f"(p1[2]), "f"(p1[3]) : "memory");
                }
                curb = b;
#pragma unroll
                for (int j = 0; j < 4; j++) { p0[j] = 0.f; p1[j] = 0.f; }
            }
#pragma unroll
            for (int j = 0; j < 4; j++) {
                p0[j] += fmaxf(accum[i][j] + bv[j], 0.f);
                p1[j] += fmaxf(accum[i][j + 4] + bv[j + 4], 0.f);
            }
        }
        if (curb >= 0) {
            float* dst0 = pool + (size_t)curb * 128 + tx * 8;
            asm volatile("red.global.add.v4.f32 [%0], {%1,%2,%3,%4};"
                         :: "l"(dst0), "f"(p0[0]), "f"(p0[1]), "f"(p0[2]), "f"(p0[3]) : "memory");
            asm volatile("red.global.add.v4.f32 [%0], {%1,%2,%3,%4};"
                         :: "l"(dst0 + 4), "f"(p1[0]), "f"(p1[1]), "f"(p1[2]), "f"(p1[3]) : "memory");
        }
    }
}

// --- count nodes per graph -------------------------------------------------
__global__ void cnt_hist(const int* __restrict__ batch, float* __restrict__ cnt, int N) {
    int i = blockIdx.x * blockDim.x + threadIdx.x;
    if (i < N) atomicAdd(&cnt[batch[i]], 1.0f);
}

// --- head MLP --------------------------------------------------------------
__global__ void mlp1(const float* __restrict__ pool, const float* __restrict__ cnt,
                     const float* __restrict__ W, const float* __restrict__ b,
                     float* __restrict__ out) {
    __shared__ float p[128];
    int g = blockIdx.x, j = threadIdx.x;
    float c = cnt[g];
    c = (c < 1.f) ? 1.f : c;
    p[j] = pool[(size_t)g * 128 + j] / c;
    __syncthreads();
    float acc = b[j];
#pragma unroll
    for (int k = 0; k < 128; k++) acc += p[k] * W[(size_t)k * 128 + j];
    out[(size_t)g * 128 + j] = acc;
}

__global__ void mlp2(const float* __restrict__ m1, const float* __restrict__ W2,
                     const float* __restrict__ b2, const float* __restrict__ gamma,
                     const float* __restrict__ beta, const float* __restrict__ outW,
                     const float* __restrict__ outb, float* __restrict__ dout) {
    __shared__ float p[128];
    __shared__ float hred[64];
    int g = blockIdx.x, j = threadIdx.x;  // 64 threads
    p[j] = m1[(size_t)g * 128 + j];
    p[j + 64] = m1[(size_t)g * 128 + 64 + j];
    __syncthreads();
    float acc = b2[j];
#pragma unroll
    for (int k = 0; k < 128; k++) acc += p[k] * W2[(size_t)k * 64 + j];
    float h = acc * rsqrtf(1.0f + 1e-5f) * gamma[j] + beta[j];
    h = fmaxf(h, 0.f);
    dout[NG + (size_t)g * 64 + j] = h;
    hred[j] = h * outW[j];
    __syncthreads();
#pragma unroll
    for (int off = 32; off >= 1; off >>= 1) {
        if (j < off) hred[j] += hred[j + off];
        __syncthreads();
    }
    if (j == 0) dout[g] = hred[0] + outb[0];
}

// ---------------------------------------------------------------------------

static inline int cdiv(long long n, int t) { return (int)((n + t - 1) / t); }

static void build_csr(const int* src, const int* dst, const float* w,
                      const float* dinv, int* cnts, int* rowptr, int* bsums,
                      int* ssrc, float* coef, int N, int E) {
    int nb = cdiv(N, 1024);
    scan_tiles<<<nb, 1024>>>(cnts, rowptr, bsums, N);
    scan_sums<<<1, 1024>>>(bsums, nb);
    scan_add<<<nb, 1024>>>(rowptr, bsums, N);
    copy_i<<<cdiv(N, 256), 256>>>(rowptr, cnts, N);  // running offsets
    scatter_edges<<<cdiv(E, 256), 256>>>(src, dst, w, dinv, cnts, ssrc, coef, E);
}

extern "C" void kernel_launch(void* const* d_in, const int* in_sizes, int n_in,
                              void* d_out, int out_size) {
    const float* x_l     = (const float*)d_in[0];
    const int*   ei_l    = (const int*)d_in[1];
    const float* w_l     = (const float*)d_in[2];
    const float* x_s     = (const float*)d_in[3];
    const int*   ei_s    = (const int*)d_in[4];
    const float* w_s     = (const float*)d_in[5];
    const int*   batch_l = (const int*)d_in[6];
    const int*   batch_s = (const int*)d_in[7];
    const float* Wa[4] = {(const float*)d_in[8],  (const float*)d_in[12],
                          (const float*)d_in[16], (const float*)d_in[20]};
    const float* ba[4] = {(const float*)d_in[9],  (const float*)d_in[13],
                          (const float*)d_in[17], (const float*)d_in[21]};
    const float* Wb[4] = {(const float*)d_in[10], (const float*)d_in[14],
                          (const float*)d_in[18], (const float*)d_in[22]};
    const float* bb[4] = {(const float*)d_in[11], (const float*)d_in[15],
                          (const float*)d_in[19], (const float*)d_in[23]};
    const float* lin1W = (const float*)d_in[24];
    const float* lin1b = (const float*)d_in[25];
    const float* lin2W = (const float*)d_in[26];
    const float* lin2b = (const float*)d_in[27];
    const float* gamma = (const float*)d_in[28];
    const float* beta  = (const float*)d_in[29];
    const float* outW  = (const float*)d_in[30];
    const float* outb  = (const float*)d_in[31];

    int El = in_sizes[2];
    int Es = in_sizes[5];
    int Nl = in_sizes[6];
    int Ns = in_sizes[7];
    const int* src_l = ei_l;
    const int* dst_l = ei_l + El;
    const int* src_s = ei_s;
    const int* dst_s = ei_s + Es;

    float *ha_l, *hb_l, *ha_s, *hb_s, *dinv_l, *dinv_s, *pool, *gcnt, *m1, *coef_l, *coef_s;
    int *rp_l, *rp_s, *cnts_l, *cnts_s, *bsums, *ssrc_l, *ssrc_s;
    cudaGetSymbolAddress((void**)&ha_l, g_a_l);
    cudaGetSymbolAddress((void**)&hb_l, g_b_l);
    cudaGetSymbolAddress((void**)&ha_s, g_a_s);
    cudaGetSymbolAddress((void**)&hb_s, g_b_s);
    cudaGetSymbolAddress((void**)&dinv_l, g_dinv_l);
    cudaGetSymbolAddress((void**)&dinv_s, g_dinv_s);
    cudaGetSymbolAddress((void**)&pool, g_pool);
    cudaGetSymbolAddress((void**)&gcnt, g_gcnt);
    cudaGetSymbolAddress((void**)&m1, g_m1);
    cudaGetSymbolAddress((void**)&rp_l, g_rp_l);
    cudaGetSymbolAddress((void**)&rp_s, g_rp_s);
    cudaGetSymbolAddress((void**)&cnts_l, g_cnts_l);
    cudaGetSymbolAddress((void**)&cnts_s, g_cnts_s);
    cudaGetSymbolAddress((void**)&bsums, g_bsums);
    cudaGetSymbolAddress((void**)&ssrc_l, g_ssrc_l);
    cudaGetSymbolAddress((void**)&coef_l, g_coef_l);
    cudaGetSymbolAddress((void**)&ssrc_s, g_ssrc_s);
    cudaGetSymbolAddress((void**)&coef_s, g_coef_s);

    // opt-in to large dynamic smem (idempotent)
    cudaFuncSetAttribute(fused_layer<128, false>, cudaFuncAttributeMaxDynamicSharedMemorySize, 160 * 1024);
    cudaFuncSetAttribute(fused_layer<128, true>,  cudaFuncAttributeMaxDynamicSharedMemorySize, 160 * 1024);
    cudaFuncSetAttribute(fused_layer<64,  false>, cudaFuncAttributeMaxDynamicSharedMemorySize, 160 * 1024);
    cudaFuncSetAttribute(fused_layer<32,  false>, cudaFuncAttributeMaxDynamicSharedMemorySize, 160 * 1024);

    const int SM128 = (128 * 132 + 16 * 128) * 4;  // 75.8 KB
    const int SM64  = (128 * 68  + 16 * 128) * 4;  // 42.9 KB
    const int SM32  = (128 * 36  + 16 * 128) * 4;  // 26.6 KB

    // --- dinv + histogram (one edge pass per graph) ---
    zero_f<<<cdiv(Nl, 256), 256>>>(dinv_l, Nl);
    zero_f<<<cdiv(Ns, 256), 256>>>(dinv_s, Ns);
    zero_i<<<cdiv(Nl, 256), 256>>>(cnts_l, Nl);
    zero_i<<<cdiv(Ns, 256), 256>>>(cnts_s, Ns);
    deg_hist<<<cdiv(El, 256), 256>>>(dst_l, w_l, dinv_l, cnts_l, El);
    deg_hist<<<cdiv(Es, 256), 256>>>(dst_s, w_s, dinv_s, cnts_s, Es);
    finish_dinv<<<cdiv(Nl, 256), 256>>>(dinv_l, Nl);
    finish_dinv<<<cdiv(Ns, 256), 256>>>(dinv_s, Ns);

    // --- CSR (built once, reused by 4 layers each) ---
    build_csr(src_l, dst_l, w_l, dinv_l, cnts_l, rp_l, bsums, ssrc_l, coef_l, Nl, El);
    build_csr(src_s, dst_s, w_s, dinv_s, cnts_s, rp_s, bsums, ssrc_s, coef_s, Ns, Es);

    // --- pool buffers zeroed (pool written by fused final layers) ---
    zero_f<<<cdiv(NG * 128, 256), 256>>>(pool, NG * 128);
    zero_f<<<cdiv(NG, 256), 256>>>(gcnt, NG);

    int gl = cdiv(Nl, 128), gs = cdiv(Ns, 128);

    // --- large branch: x -> a -> b -> a -> (pool)  [ping-pong, no in-place] ---
    fused_layer<64, false><<<gl, 256, SM64>>>(x_l, rp_l, ssrc_l, coef_l, dinv_l,
                                              Wa[0], ba[0], ha_l, nullptr, nullptr, Nl);
    fused_layer<128, false><<<gl, 256, SM128>>>(ha_l, rp_l, ssrc_l, coef_l, dinv_l,
                                                Wa[1], ba[1], hb_l, nullptr, nullptr, Nl);
    fused_layer<128, false><<<gl, 256, SM128>>>(hb_l, rp_l, ssrc_l, coef_l, dinv_l,
                                                Wa[2], ba[2], ha_l, nullptr, nullptr, Nl);
    fused_layer<128, true><<<gl, 256, SM128>>>(ha_l, rp_l, ssrc_l, coef_l, dinv_l,
                                               Wa[3], ba[3], nullptr, batch_l, pool, Nl);

    // --- small branch ---
    fused_layer<32, false><<<gs, 256, SM32>>>(x_s, rp_s, ssrc_s, coef_s, dinv_s,
                                              Wb[0], bb[0], ha_s, nullptr, nullptr, Ns);
    fused_layer<128, false><<<gs, 256, SM128>>>(ha_s, rp_s, ssrc_s, coef_s, dinv_s,
                                                Wb[1], bb[1], hb_s, nullptr, nullptr, Ns);
    fused_layer<128, false><<<gs, 256, SM128>>>(hb_s, rp_s, ssrc_s, coef_s, dinv_s,
                                                Wb[2], bb[2], ha_s, nullptr, nullptr, Ns);
    fused_layer<128, true><<<gs, 256, SM128>>>(ha_s, rp_s, ssrc_s, coef_s, dinv_s,
                                               Wb[3], bb[3], nullptr, batch_s, pool, Ns);

    // --- node counts + head MLP ---
    cnt_hist<<<cdiv(Nl, 256), 256>>>(batch_l, gcnt, Nl);
    cnt_hist<<<cdiv(Ns, 256), 256>>>(batch_s, gcnt, Ns);
    mlp1<<<NG, 128>>>(pool, gcnt, lin1W, lin1b, m1);
    mlp2<<<NG, 64>>>(m1, lin2W, lin2b, gamma, beta, outW, outb, (float*)d_out);
}

// round 11
// speedup vs baseline: 1.6855x; 1.6855x over previous
#include <cuda_runtime.h>
#include <cuda_bf16.h>
#include <stdint.h>
#include <math.h>

// ---------------------------------------------------------------------------
// GCN_trad round 8:
//   - CSR agg (fp32 accum) -> z written as bf16 hi/lo split
//   - mma.sync bf16 tensor-core GEMM (hi*hi + hi*lo + lo*hi), fp32 accum
//     (tcgen05 is NOT available: harness targets compute_103 family, which
//      gates all tcgen05.* — mma.sync/ldmatrix are baseline sm_80+.)
//   - pooling epilogue fused into final-layer GEMM
// ---------------------------------------------------------------------------

#define NLMAX 100000
#define NSMAX 50000
#define ELMAX 1600000
#define ESMAX 800000
#define NG    512

__device__ __align__(256) float    g_h_l[(size_t)NLMAX * 128];
__device__ __align__(256) float    g_h_s[(size_t)NSMAX * 128];
__device__ __align__(256) uint32_t g_zh[(size_t)NLMAX * 64];
__device__ __align__(256) uint32_t g_zl[(size_t)NLMAX * 64];
__device__ __align__(256) __nv_bfloat16 g_wth[128 * 128];
__device__ __align__(256) __nv_bfloat16 g_wtl[128 * 128];
__device__ __align__(256) float g_dinv_l[NLMAX];
__device__ __align__(256) float g_dinv_s[NSMAX];
__device__ __align__(256) float g_pool[NG * 128];
__device__ __align__(256) float g_gcnt[NG];
__device__ __align__(256) float g_m1[NG * 128];

__device__ __align__(256) int   g_rp_l[NLMAX + 1];
__device__ __align__(256) int   g_rp_s[NSMAX + 1];
__device__ __align__(256) int   g_cnts_l[NLMAX];
__device__ __align__(256) int   g_cnts_s[NSMAX];
__device__ __align__(256) int   g_bsums[1024];
__device__ __align__(256) int   g_ssrc_l[ELMAX];
__device__ __align__(256) float g_coef_l[ELMAX];
__device__ __align__(256) int   g_ssrc_s[ESMAX];
__device__ __align__(256) float g_coef_s[ESMAX];

// ---------------------------------------------------------------------------

__device__ __forceinline__ uint32_t smem_to_u32(const void* p) {
    uint32_t a;
    asm("{ .reg .u64 t; cvta.to.shared.u64 t, %1; cvt.u32.u64 %0, t; }"
        : "=r"(a) : "l"(p));
    return a;
}

__global__ void zero_f(float* __restrict__ p, int n) {
    int i = blockIdx.x * blockDim.x + threadIdx.x;
    if (i < n) p[i] = 0.f;
}
__global__ void zero_i(int* __restrict__ p, int n) {
    int i = blockIdx.x * blockDim.x + threadIdx.x;
    if (i < n) p[i] = 0;
}
__global__ void copy_i(const int* __restrict__ a, int* __restrict__ b, int n) {
    int i = blockIdx.x * blockDim.x + threadIdx.x;
    if (i < n) b[i] = a[i];
}
__global__ void deg_hist(const int* __restrict__ dst, const float* __restrict__ w,
                         float* __restrict__ deg, int* __restrict__ cnt, int E) {
    int e = blockIdx.x * blockDim.x + threadIdx.x;
    if (e < E) { int d = dst[e]; atomicAdd(&deg[d], w[e]); atomicAdd(&cnt[d], 1); }
}
__global__ void finish_dinv(float* __restrict__ d, int n) {
    int i = blockIdx.x * blockDim.x + threadIdx.x;
    if (i < n) d[i] = rsqrtf(1.0f + d[i]);
}

__global__ void scan_tiles(const int* __restrict__ in, int* __restrict__ out,
                           int* __restrict__ bsums, int n) {
    __shared__ int sh[1024];
    int tid = threadIdx.x, i = blockIdx.x * 1024 + tid;
    sh[tid] = (i < n) ? in[i] : 0;
    __syncthreads();
#pragma unroll
    for (int off = 1; off < 1024; off <<= 1) {
        int t = (tid >= off) ? sh[tid - off] : 0;
        __syncthreads(); sh[tid] += t; __syncthreads();
    }
    if (i < n) out[i + 1] = sh[tid];
    if (tid == 1023) bsums[blockIdx.x] = sh[1023];
}
__global__ void scan_sums(int* __restrict__ bsums, int nb) {
    __shared__ int sh[1024];
    int tid = threadIdx.x;
    sh[tid] = (tid < nb) ? bsums[tid] : 0;
    __syncthreads();
#pragma unroll
    for (int off = 1; off < 1024; off <<= 1) {
        int t = (tid >= off) ? sh[tid - off] : 0;
        __syncthreads(); sh[tid] += t; __syncthreads();
    }
    if (tid < nb) bsums[tid] = sh[tid];
}
__global__ void scan_add(int* __restrict__ out, const int* __restrict__ bsums, int n) {
    int i = blockIdx.x * blockDim.x + threadIdx.x;
    if (i == 0) out[0] = 0;
    if (i < n) { int b = i >> 10; if (b > 0) out[i + 1] += bsums[b - 1]; }
}
__global__ void scatter_edges(const int* __restrict__ src, const int* __restrict__ dst,
                              const float* __restrict__ w, const float* __restrict__ dinv,
                              int* __restrict__ off, int* __restrict__ ssrc,
                              float* __restrict__ coef, int E) {
    int e = blockIdx.x * blockDim.x + threadIdx.x;
    if (e >= E) return;
    int s = src[e], d = dst[e];
    int p = atomicAdd(&off[d], 1);
    ssrc[p] = s;
    coef[p] = w[e] * __ldg(&dinv[s]) * __ldg(&dinv[d]);
}

// --- vector helpers --------------------------------------------------------

template <int VW> struct Vec;
template <> struct Vec<4> { using T = float4; };
template <> struct Vec<2> { using T = float2; };
template <> struct Vec<1> { using T = float;  };

__device__ __forceinline__ float4 vscale(float4 v, float c) {
    return make_float4(v.x * c, v.y * c, v.z * c, v.w * c);
}
__device__ __forceinline__ float2 vscale(float2 v, float c) { return make_float2(v.x * c, v.y * c); }
__device__ __forceinline__ float vscale(float v, float c) { return v * c; }
__device__ __forceinline__ float4 vfma(float4 a, float c, float4 v) {
    return make_float4(fmaf(c, v.x, a.x), fmaf(c, v.y, a.y), fmaf(c, v.z, a.z), fmaf(c, v.w, a.w));
}
__device__ __forceinline__ float2 vfma(float2 a, float c, float2 v) {
    return make_float2(fmaf(c, v.x, a.x), fmaf(c, v.y, a.y));
}
__device__ __forceinline__ float vfma(float a, float c, float v) { return fmaf(c, v, a); }

// hi/lo bf16 split stores
__device__ __forceinline__ void split_pair(float a, float b, __nv_bfloat162& h, __nv_bfloat162& l) {
    __nv_bfloat16 ha = __float2bfloat16(a), hb = __float2bfloat16(b);
    h.x = ha; h.y = hb;
    l.x = __float2bfloat16(a - __bfloat162float(ha));
    l.y = __float2bfloat16(b - __bfloat162float(hb));
}
__device__ __forceinline__ void store_split(uint32_t* zh, uint32_t* zl, int row, int lane, float4 a) {
    __nv_bfloat162 h0, l0, h1, l1;
    split_pair(a.x, a.y, h0, l0);
    split_pair(a.z, a.w, h1, l1);
    __nv_bfloat162* ph = (__nv_bfloat162*)zh + (size_t)row * 64 + lane * 2;
    __nv_bfloat162* pl = (__nv_bfloat162*)zl + (size_t)row * 64 + lane * 2;
    ph[0] = h0; ph[1] = h1;
    pl[0] = l0; pl[1] = l1;
}
__device__ __forceinline__ void store_split(uint32_t* zh, uint32_t* zl, int row, int lane, float2 a) {
    __nv_bfloat162 h0, l0;
    split_pair(a.x, a.y, h0, l0);
    ((__nv_bfloat162*)zh)[(size_t)row * 32 + lane] = h0;
    ((__nv_bfloat162*)zl)[(size_t)row * 32 + lane] = l0;
}
__device__ __forceinline__ void store_split(uint32_t* zh, uint32_t* zl, int row, int lane, float a) {
    __nv_bfloat16 h = __float2bfloat16(a);
    ((__nv_bfloat16*)zh)[(size_t)row * 32 + lane] = h;
    ((__nv_bfloat16*)zl)[(size_t)row * 32 + lane] = __float2bfloat16(a - __bfloat162float(h));
}

// --- CSR aggregation: warp per destination row, bf16 hi/lo split output ----
template <int VW>
__global__ __launch_bounds__(256) void agg_csr(
    const typename Vec<VW>::T* __restrict__ h, const int* __restrict__ rowptr,
    const int* __restrict__ ssrc, const float* __restrict__ coef,
    const float* __restrict__ dinv, uint32_t* __restrict__ zh,
    uint32_t* __restrict__ zl, int N) {
    using VT = typename Vec<VW>::T;
    int wgid = (blockIdx.x * blockDim.x + threadIdx.x) >> 5;
    int lane = threadIdx.x & 31;
    if (wgid >= N) return;
    float di = __ldg(&dinv[wgid]);
    VT acc = vscale(h[(size_t)wgid * 32 + lane], di * di);
    int e = __ldg(&rowptr[wgid]);
    int e1 = __ldg(&rowptr[wgid + 1]);
    for (; e + 1 < e1; e += 2) {
        int s0 = __ldg(&ssrc[e]);
        int s1 = __ldg(&ssrc[e + 1]);
        float c0 = __ldg(&coef[e]);
        float c1 = __ldg(&coef[e + 1]);
        VT v0 = h[(size_t)s0 * 32 + lane];
        VT v1 = h[(size_t)s1 * 32 + lane];
        acc = vfma(acc, c0, v0);
        acc = vfma(acc, c1, v1);
    }
    if (e < e1) {
        int s0 = __ldg(&ssrc[e]);
        acc = vfma(acc, __ldg(&coef[e]), h[(size_t)s0 * 32 + lane]);
    }
    store_split(zh, zl, wgid, lane, acc);
}

// --- W^T hi/lo build: wt[n*K+k] = split(W[k*128+n]) ------------------------
__global__ void wt_build(const float* __restrict__ W, __nv_bfloat16* __restrict__ th,
                         __nv_bfloat16* __restrict__ tl, int K) {
    int i = blockIdx.x * blockDim.x + threadIdx.x;
    if (i >= 128 * K) return;
    int n = i / K, k = i % K;
    float v = __ldg(&W[(size_t)k * 128 + n]);
    __nv_bfloat16 h = __float2bfloat16(v);
    th[i] = h;
    tl[i] = __float2bfloat16(v - __bfloat162float(h));
}

// ---------------------------------------------------------------------------
// mma.sync bf16 GEMM: H[128-tile,128] = relu((Ahi+Alo)[*,K] @ (Bhi+Blo)^T + b)
// 8 warps, warp = 16 rows x 128 cols. A fragments straight from global zh/zl,
// B (W^T) hi/lo in padded smem via ldmatrix.
// ---------------------------------------------------------------------------
__device__ __forceinline__ void mma_bf16(float* d, uint32_t a0, uint32_t a1,
                                         uint32_t a2, uint32_t a3,
                                         uint32_t b0, uint32_t b1) {
    asm volatile("mma.sync.aligned.m16n8k16.row.col.f32.bf16.bf16.f32 "
                 "{%0,%1,%2,%3}, {%4,%5,%6,%7}, {%8,%9}, {%0,%1,%2,%3};"
                 : "+f"(d[0]), "+f"(d[1]), "+f"(d[2]), "+f"(d[3])
                 : "r"(a0), "r"(a1), "r"(a2), "r"(a3), "r"(b0), "r"(b1));
}
__device__ __forceinline__ void ldm_x2(uint32_t& b0, uint32_t& b1, uint32_t addr) {
    asm volatile("ldmatrix.sync.aligned.m8n8.x2.shared.b16 {%0,%1}, [%2];"
                 : "=r"(b0), "=r"(b1) : "r"(addr));
}

template <int K, bool POOL>
__global__ __launch_bounds__(256) void gemm_mma(
    const uint32_t* __restrict__ zhi, const uint32_t* __restrict__ zlo,
    const __nv_bfloat16* __restrict__ wthi, const __nv_bfloat16* __restrict__ wtlo,
    const float* __restrict__ bias, float* __restrict__ Hout,
    const int* __restrict__ batch, float* __restrict__ pool, int N) {

    constexpr int KW = K / 2;      // u32 per A row
    constexpr int SK = K + 8;      // smem row stride (elements)
    constexpr int NK = K / 16;     // k-steps

    extern __shared__ __align__(16) __nv_bfloat16 sB[];
    __nv_bfloat16* Bh = sB;
    __nv_bfloat16* Bl = sB + 128 * SK;

    int tid = threadIdx.x;
    for (int i = tid; i < 128 * (K / 8); i += 256) {
        int n = i / (K / 8), c = (i % (K / 8)) * 8;
        *(uint4*)&Bh[n * SK + c] = *(const uint4*)&wthi[(size_t)n * K + c];
        *(uint4*)&Bl[n * SK + c] = *(const uint4*)&wtlo[(size_t)n * K + c];
    }
    __syncthreads();

    int warp = tid >> 5, lane = tid & 31;
    int m0 = blockIdx.x * 128 + warp * 16;
    int qp = lane & 3;
    int r0 = m0 + (lane >> 2);
    int r1 = r0 + 8;
    bool v0 = r0 < N, v1 = r1 < N;

    uint32_t sbh = smem_to_u32(Bh);
    uint32_t sbl = smem_to_u32(Bl);
    int l16 = lane & 15;
    uint32_t loff = (uint32_t)(((l16 & 7) * SK + (l16 >> 3) * 8) * 2);

    float acc[16][4];
#pragma unroll
    for (int t = 0; t < 16; t++)
#pragma unroll
        for (int j = 0; j < 4; j++) acc[t][j] = 0.f;

    const uint32_t* ph0 = zhi + (size_t)(v0 ? r0 : 0) * KW + qp;
    const uint32_t* ph1 = zhi + (size_t)(v1 ? r1 : 0) * KW + qp;
    const uint32_t* pl0 = zlo + (size_t)(v0 ? r0 : 0) * KW + qp;
    const uint32_t* pl1 = zlo + (size_t)(v1 ? r1 : 0) * KW + qp;

#pragma unroll
    for (int ks = 0; ks < NK; ks++) {
        uint32_t ah0 = 0, ah1 = 0, ah2 = 0, ah3 = 0;
        uint32_t al0 = 0, al1 = 0, al2 = 0, al3 = 0;
        if (v0) { ah0 = ph0[ks * 8]; ah2 = ph0[ks * 8 + 4];
                  al0 = pl0[ks * 8]; al2 = pl0[ks * 8 + 4]; }
        if (v1) { ah1 = ph1[ks * 8]; ah3 = ph1[ks * 8 + 4];
                  al1 = pl1[ks * 8]; al3 = pl1[ks * 8 + 4]; }
        uint32_t kb = (uint32_t)(ks * 32);  // ks*16 elements * 2B
#pragma unroll
        for (int nt = 0; nt < 16; nt++) {
            uint32_t off = (uint32_t)(nt * 8 * SK * 2) + kb + loff;
            uint32_t bh0, bh1, bl0, bl1;
            ldm_x2(bh0, bh1, sbh + off);
            ldm_x2(bl0, bl1, sbl + off);
            mma_bf16(acc[nt], ah0, ah1, ah2, ah3, bh0, bh1);
            mma_bf16(acc[nt], ah0, ah1, ah2, ah3, bl0, bl1);
            mma_bf16(acc[nt], al0, al1, al2, al3, bh0, bh1);
        }
    }

    int pb0 = -1, pb1 = -1;
    if (POOL) {
        if (v0) pb0 = __ldg(&batch[r0]);
        if (v1) pb1 = __ldg(&batch[r1]);
    }
#pragma unroll
    for (int nt = 0; nt < 16; nt++) {
        int col = nt * 8 + 2 * qp;
        float2 bv = *(const float2*)&bias[col];
        float ox = fmaxf(acc[nt][0] + bv.x, 0.f);
        float oy = fmaxf(acc[nt][1] + bv.y, 0.f);
        float px = fmaxf(acc[nt][2] + bv.x, 0.f);
        float py = fmaxf(acc[nt][3] + bv.y, 0.f);
        if (!POOL) {
            if (v0) { float2 o = make_float2(ox, oy);
                      *(float2*)(Hout + (size_t)r0 * 128 + col) = o; }
            if (v1) { float2 o = make_float2(px, py);
                      *(float2*)(Hout + (size_t)r1 * 128 + col) = o; }
        } else {
            if (v0) {
                float* dp = pool + (size_t)pb0 * 128 + col;
                asm volatile("red.global.add.v2.f32 [%0], {%1,%2};"
                             :: "l"(dp), "f"(ox), "f"(oy) : "memory");
            }
            if (v1) {
                float* dp = pool + (size_t)pb1 * 128 + col;
                asm volatile("red.global.add.v2.f32 [%0], {%1,%2};"
                             :: "l"(dp), "f"(px), "f"(py) : "memory");
            }
        }
    }
}

// --- counts + head MLP -----------------------------------------------------
__global__ void cnt_hist(const int* __restrict__ batch, float* __restrict__ cnt, int N) {
    int i = blockIdx.x * blockDim.x + threadIdx.x;
    if (i < N) atomicAdd(&cnt[batch[i]], 1.0f);
}
__global__ void mlp1(const float* __restrict__ pool, const float* __restrict__ cnt,
                     const float* __restrict__ W, const float* __restrict__ b,
                     float* __restrict__ out) {
    __shared__ float p[128];
    int g = blockIdx.x, j = threadIdx.x;
    float c = cnt[g];
    c = (c < 1.f) ? 1.f : c;
    p[j] = pool[(size_t)g * 128 + j] / c;
    __syncthreads();
    float acc = b[j];
#pragma unroll
    for (int k = 0; k < 128; k++) acc += p[k] * W[(size_t)k * 128 + j];
    out[(size_t)g * 128 + j] = acc;
}
__global__ void mlp2(const float* __restrict__ m1, const float* __restrict__ W2,
                     const float* __restrict__ b2, const float* __restrict__ gamma,
                     const float* __restrict__ beta, const float* __restrict__ outW,
                     const float* __restrict__ outb, float* __restrict__ dout) {
    __shared__ float p[128];
    __shared__ float hred[64];
    int g = blockIdx.x, j = threadIdx.x;  // 64 threads
    p[j] = m1[(size_t)g * 128 + j];
    p[j + 64] = m1[(size_t)g * 128 + 64 + j];
    __syncthreads();
    float acc = b2[j];
#pragma unroll
    for (int k = 0; k < 128; k++) acc += p[k] * W2[(size_t)k * 64 + j];
    float h = acc * rsqrtf(1.0f + 1e-5f) * gamma[j] + beta[j];
    h = fmaxf(h, 0.f);
    dout[NG + (size_t)g * 64 + j] = h;
    hred[j] = h * outW[j];
    __syncthreads();
#pragma unroll
    for (int off = 32; off >= 1; off >>= 1) {
        if (j < off) hred[j] += hred[j + off];
        __syncthreads();
    }
    if (j == 0) dout[g] = hred[0] + outb[0];
}

// ---------------------------------------------------------------------------

static inline int cdiv(long long n, int t) { return (int)((n + t - 1) / t); }

static void build_csr(const int* src, const int* dst, const float* w,
                      const float* dinv, int* cnts, int* rowptr, int* bsums,
                      int* ssrc, float* coef, int N, int E) {
    int nb = cdiv(N, 1024);
    scan_tiles<<<nb, 1024>>>(cnts, rowptr, bsums, N);
    scan_sums<<<1, 1024>>>(bsums, nb);
    scan_add<<<nb, 1024>>>(rowptr, bsums, N);
    copy_i<<<cdiv(N, 256), 256>>>(rowptr, cnts, N);
    scatter_edges<<<cdiv(E, 256), 256>>>(src, dst, w, dinv, cnts, ssrc, coef, E);
}

extern "C" void kernel_launch(void* const* d_in, const int* in_sizes, int n_in,
                              void* d_out, int out_size) {
    const float* x_l     = (const float*)d_in[0];
    const int*   ei_l    = (const int*)d_in[1];
    const float* w_l     = (const float*)d_in[2];
    const float* x_s     = (const float*)d_in[3];
    const int*   ei_s    = (const int*)d_in[4];
    const float* w_s     = (const float*)d_in[5];
    const int*   batch_l = (const int*)d_in[6];
    const int*   batch_s = (const int*)d_in[7];
    const float* Wa[4] = {(const float*)d_in[8],  (const float*)d_in[12],
                          (const float*)d_in[16], (const float*)d_in[20]};
    const float* ba[4] = {(const float*)d_in[9],  (const float*)d_in[13],
                          (const float*)d_in[17], (const float*)d_in[21]};
    const float* Wb[4] = {(const float*)d_in[10], (const float*)d_in[14],
                          (const float*)d_in[18], (const float*)d_in[22]};
    const float* bb[4] = {(const float*)d_in[11], (const float*)d_in[15],
                          (const float*)d_in[19], (const float*)d_in[23]};
    const float* lin1W = (const float*)d_in[24];
    const float* lin1b = (const float*)d_in[25];
    const float* lin2W = (const float*)d_in[26];
    const float* lin2b = (const float*)d_in[27];
    const float* gamma = (const float*)d_in[28];
    const float* beta  = (const float*)d_in[29];
    const float* outW  = (const float*)d_in[30];
    const float* outb  = (const float*)d_in[31];

    int El = in_sizes[2], Es = in_sizes[5];
    int Nl = in_sizes[6], Ns = in_sizes[7];
    const int* src_l = ei_l;
    const int* dst_l = ei_l + El;
    const int* src_s = ei_s;
    const int* dst_s = ei_s + Es;

    float *h_l, *h_s, *dinv_l, *dinv_s, *pool, *gcnt, *m1, *coef_l, *coef_s;
    uint32_t *zh, *zl;
    __nv_bfloat16 *wth, *wtl;
    int *rp_l, *rp_s, *cnts_l, *cnts_s, *bsums, *ssrc_l, *ssrc_s;
    cudaGetSymbolAddress((void**)&h_l, g_h_l);
    cudaGetSymbolAddress((void**)&h_s, g_h_s);
    cudaGetSymbolAddress((void**)&zh, g_zh);
    cudaGetSymbolAddress((void**)&zl, g_zl);
    cudaGetSymbolAddress((void**)&wth, g_wth);
    cudaGetSymbolAddress((void**)&wtl, g_wtl);
    cudaGetSymbolAddress((void**)&dinv_l, g_dinv_l);
    cudaGetSymbolAddress((void**)&dinv_s, g_dinv_s);
    cudaGetSymbolAddress((void**)&pool, g_pool);
    cudaGetSymbolAddress((void**)&gcnt, g_gcnt);
    cudaGetSymbolAddress((void**)&m1, g_m1);
    cudaGetSymbolAddress((void**)&rp_l, g_rp_l);
    cudaGetSymbolAddress((void**)&rp_s, g_rp_s);
    cudaGetSymbolAddress((void**)&cnts_l, g_cnts_l);
    cudaGetSymbolAddress((void**)&cnts_s, g_cnts_s);
    cudaGetSymbolAddress((void**)&bsums, g_bsums);
    cudaGetSymbolAddress((void**)&ssrc_l, g_ssrc_l);
    cudaGetSymbolAddress((void**)&coef_l, g_coef_l);
    cudaGetSymbolAddress((void**)&ssrc_s, g_ssrc_s);
    cudaGetSymbolAddress((void**)&coef_s, g_coef_s);

    // dynamic smem: 2 * 128 * (K+8) * 2 bytes
    const int SMEM128 = 2 * 128 * (128 + 8) * 2;  // 69,632
    const int SMEM64  = 2 * 128 * (64 + 8) * 2;   // 36,864
    const int SMEM32  = 2 * 128 * (32 + 8) * 2;   // 20,480
    cudaFuncSetAttribute(gemm_mma<128, false>, cudaFuncAttributeMaxDynamicSharedMemorySize, SMEM128);
    cudaFuncSetAttribute(gemm_mma<128, true>,  cudaFuncAttributeMaxDynamicSharedMemorySize, SMEM128);
    cudaFuncSetAttribute(gemm_mma<64,  false>, cudaFuncAttributeMaxDynamicSharedMemorySize, SMEM64);
    cudaFuncSetAttribute(gemm_mma<32,  false>, cudaFuncAttributeMaxDynamicSharedMemorySize, SMEM32);

    // --- dinv + histogram ---
    zero_f<<<cdiv(Nl, 256), 256>>>(dinv_l, Nl);
    zero_f<<<cdiv(Ns, 256), 256>>>(dinv_s, Ns);
    zero_i<<<cdiv(Nl, 256), 256>>>(cnts_l, Nl);
    zero_i<<<cdiv(Ns, 256), 256>>>(cnts_s, Ns);
    deg_hist<<<cdiv(El, 256), 256>>>(dst_l, w_l, dinv_l, cnts_l, El);
    deg_hist<<<cdiv(Es, 256), 256>>>(dst_s, w_s, dinv_s, cnts_s, Es);
    finish_dinv<<<cdiv(Nl, 256), 256>>>(dinv_l, Nl);
    finish_dinv<<<cdiv(Ns, 256), 256>>>(dinv_s, Ns);

    // --- CSR ---
    build_csr(src_l, dst_l, w_l, dinv_l, cnts_l, rp_l, bsums, ssrc_l, coef_l, Nl, El);
    build_csr(src_s, dst_s, w_s, dinv_s, cnts_s, rp_s, bsums, ssrc_s, coef_s, Ns, Es);

    zero_f<<<cdiv(NG * 128, 256), 256>>>(pool, NG * 128);
    zero_f<<<cdiv(NG, 256), 256>>>(gcnt, NG);

    int gl = cdiv(Nl, 128), gs = cdiv(Ns, 128);
    long long wl = (long long)Nl * 32, ws = (long long)Ns * 32;

    // --- large branch: 64 -> 128 x3 (last pooled) ---
    wt_build<<<cdiv(128 * 64, 256), 256>>>(Wa[0], wth, wtl, 64);
    agg_csr<2><<<cdiv(wl, 256), 256>>>((const float2*)x_l, rp_l, ssrc_l, coef_l, dinv_l, zh, zl, Nl);
    gemm_mma<64, false><<<gl, 256, SMEM64>>>(zh, zl, wth, wtl, ba[0], h_l, nullptr, nullptr, Nl);
    for (int L = 1; L < 4; L++) {
        wt_build<<<cdiv(128 * 128, 256), 256>>>(Wa[L], wth, wtl, 128);
        agg_csr<4><<<cdiv(wl, 256), 256>>>((const float4*)h_l, rp_l, ssrc_l, coef_l, dinv_l, zh, zl, Nl);
        if (L < 3)
            gemm_mma<128, false><<<gl, 256, SMEM128>>>(zh, zl, wth, wtl, ba[L], h_l, nullptr, nullptr, Nl);
        else
            gemm_mma<128, true><<<gl, 256, SMEM128>>>(zh, zl, wth, wtl, ba[L], nullptr, batch_l, pool, Nl);
    }

    // --- small branch: 32 -> 128 x3 (last pooled) ---
    wt_build<<<cdiv(128 * 32, 256), 256>>>(Wb[0], wth, wtl, 32);
    agg_csr<1><<<cdiv(ws, 256), 256>>>(x_s, rp_s, ssrc_s, coef_s, dinv_s, zh, zl, Ns);
    gemm_mma<32, false><<<gs, 256, SMEM32>>>(zh, zl, wth, wtl, bb[0], h_s, nullptr, nullptr, Ns);
    for (int L = 1; L < 4; L++) {
        wt_build<<<cdiv(128 * 128, 256), 256>>>(Wb[L], wth, wtl, 128);
        agg_csr<4><<<cdiv(ws, 256), 256>>>((const float4*)h_s, rp_s, ssrc_s, coef_s, dinv_s, zh, zl, Ns);
        if (L < 3)
            gemm_mma<128, false><<<gs, 256, SMEM128>>>(zh, zl, wth, wtl, bb[L], h_s, nullptr, nullptr, Ns);
        else
            gemm_mma<128, true><<<gs, 256, SMEM128>>>(zh, zl, wth, wtl, bb[L], nullptr, batch_s, pool, Ns);
    }

    // --- counts + head MLP ---
    cnt_hist<<<cdiv(Nl, 256), 256>>>(batch_l, gcnt, Nl);
    cnt_hist<<<cdiv(Ns, 256), 256>>>(batch_s, gcnt, Ns);
    mlp1<<<NG, 128>>>(pool, gcnt, lin1W, lin1b, m1);
    mlp2<<<NG, 64>>>(m1, lin2W, lin2b, gamma, beta, outW, outb, (float*)d_out);
}